// round 7
// baseline (speedup 1.0000x reference)
#include <cuda_runtime.h>
#include <cuda_bf16.h>
#include <mma.h>
#include <cstdint>

using namespace nvcuda;

#define T_SEQ 512
#define B_SZ  256
#define IN_D  64
#define H_D   128
#define G4    512
#define TB    (T_SEQ * B_SZ)

__device__ float g_bufA[TB * H_D];
__device__ float g_bufB[TB * H_D];
__device__ float g_pre [TB * G4];

// ---------------- helpers ----------------
__device__ __forceinline__ void fma2(unsigned long long &acc,
                                     unsigned long long a, unsigned long long b) {
    asm("fma.rn.f32x2 %0, %1, %2, %3;" : "=l"(acc) : "l"(a), "l"(b), "l"(acc));
}
__device__ __forceinline__ unsigned long long pack2(float lo, float hi) {
    unsigned long long r;
    asm("mov.b64 %0, {%1, %2};" : "=l"(r) : "f"(lo), "f"(hi));
    return r;
}
__device__ __forceinline__ float sum2(unsigned long long v) {
    float lo, hi;
    asm("mov.b64 {%0, %1}, %2;" : "=f"(lo), "=f"(hi) : "l"(v));
    return lo + hi;
}
__device__ __forceinline__ float fsig(float x) {
    return __fdividef(1.0f, 1.0f + __expf(-x));
}
__device__ __forceinline__ float ftanh(float x) {
    return __fdividef(2.0f, 1.0f + __expf(-2.0f * x)) - 1.0f;
}
// split two floats into bf16 hi / lo pairs
__device__ __forceinline__ void split2(float a, float b,
                                       __nv_bfloat162 &h, __nv_bfloat162 &l) {
    const __nv_bfloat16 ha = __float2bfloat16_rn(a);
    const __nv_bfloat16 hb = __float2bfloat16_rn(b);
    h.x = ha; h.y = hb;
    l.x = __float2bfloat16_rn(a - __bfloat162float(ha));
    l.y = __float2bfloat16_rn(b - __bfloat162float(hb));
}

// ============================================================================
// pregemm: pre[TB,512] = X[TB,K] @ W[512,K]^T + bih + bhh
// wmma bf16 hi/lo split (3 mma per k-tile). CTA tile 128(M) x 128(N), full K
// in smem. 256 threads = 8 warps as 4(m) x 2(n), warp tile 32 x 64.
// grid = (TB/128) * 4, blockIdx = m*4 + n so A tiles hit L2 across N-CTAs.
// ============================================================================
template<int K>
__global__ void __launch_bounds__(256, 1)
pregemm(const float* __restrict__ X, const float* __restrict__ W,
        const float* __restrict__ bih, const float* __restrict__ bhh,
        float* __restrict__ pre)
{
    extern __shared__ __align__(256) char smp[];
    float* bias = (float*)smp;                               // 128 f32
    __nv_bfloat16* Ah = (__nv_bfloat16*)(smp + 512);         // [128][K]
    __nv_bfloat16* Al = Ah + 128 * K;
    __nv_bfloat16* Bh = Al + 128 * K;                        // [128][K]
    __nv_bfloat16* Bl = Bh + 128 * K;
    float* Dsm = (float*)(smp + 512);                        // [128][128] reuse

    const int tid = threadIdx.x;
    const int wid = tid >> 5;
    const int m0 = (int)(blockIdx.x >> 2) * 128;
    const int n0 = (int)(blockIdx.x & 3) * 128;

    if (tid < 128) bias[tid] = bih[n0 + tid] + bhh[n0 + tid];

    // load + split A (X tile) and B (W tile) into smem
    for (int i = tid; i < 128 * K / 4; i += 256) {
        const int r = i / (K / 4), c4 = (i % (K / 4)) * 4;
        float4 v = *(const float4*)(X + (size_t)(m0 + r) * K + c4);
        __nv_bfloat162 h0, l0, h1, l1;
        split2(v.x, v.y, h0, l0);
        split2(v.z, v.w, h1, l1);
        *(__nv_bfloat162*)(Ah + r * K + c4)     = h0;
        *(__nv_bfloat162*)(Ah + r * K + c4 + 2) = h1;
        *(__nv_bfloat162*)(Al + r * K + c4)     = l0;
        *(__nv_bfloat162*)(Al + r * K + c4 + 2) = l1;
    }
    for (int i = tid; i < 128 * K / 4; i += 256) {
        const int r = i / (K / 4), c4 = (i % (K / 4)) * 4;
        float4 v = *(const float4*)(W + (size_t)(n0 + r) * K + c4);
        __nv_bfloat162 h0, l0, h1, l1;
        split2(v.x, v.y, h0, l0);
        split2(v.z, v.w, h1, l1);
        *(__nv_bfloat162*)(Bh + r * K + c4)     = h0;
        *(__nv_bfloat162*)(Bh + r * K + c4 + 2) = h1;
        *(__nv_bfloat162*)(Bl + r * K + c4)     = l0;
        *(__nv_bfloat162*)(Bl + r * K + c4 + 2) = l1;
    }
    __syncthreads();

    const int wm = wid >> 1;    // 0..3 -> m rows [wm*32, +32)
    const int wn = wid & 1;     // 0..1 -> n cols [wn*64, +64)

    wmma::fragment<wmma::accumulator, 16, 16, 16, float> acc[2][4];
#pragma unroll
    for (int mi = 0; mi < 2; mi++)
#pragma unroll
        for (int ni = 0; ni < 4; ni++) wmma::fill_fragment(acc[mi][ni], 0.0f);

#pragma unroll
    for (int ks = 0; ks < K / 16; ks++) {
        wmma::fragment<wmma::matrix_a, 16, 16, 16, __nv_bfloat16,
                       wmma::row_major> ah[2], al[2];
#pragma unroll
        for (int mi = 0; mi < 2; mi++) {
            wmma::load_matrix_sync(ah[mi],
                Ah + (wm * 32 + mi * 16) * K + ks * 16, K);
            wmma::load_matrix_sync(al[mi],
                Al + (wm * 32 + mi * 16) * K + ks * 16, K);
        }
#pragma unroll
        for (int ni = 0; ni < 4; ni++) {
            wmma::fragment<wmma::matrix_b, 16, 16, 16, __nv_bfloat16,
                           wmma::col_major> bhf, blf;
            wmma::load_matrix_sync(bhf,
                Bh + (wn * 64 + ni * 16) * K + ks * 16, K);
            wmma::load_matrix_sync(blf,
                Bl + (wn * 64 + ni * 16) * K + ks * 16, K);
#pragma unroll
            for (int mi = 0; mi < 2; mi++) {
                wmma::mma_sync(acc[mi][ni], ah[mi], bhf, acc[mi][ni]);  // hi*hi
                wmma::mma_sync(acc[mi][ni], ah[mi], blf, acc[mi][ni]);  // hi*lo
                wmma::mma_sync(acc[mi][ni], al[mi], bhf, acc[mi][ni]);  // lo*hi
            }
        }
    }
    __syncthreads();   // all smem A/B reads done; reuse as D

#pragma unroll
    for (int mi = 0; mi < 2; mi++)
#pragma unroll
        for (int ni = 0; ni < 4; ni++)
            wmma::store_matrix_sync(
                Dsm + (wm * 32 + mi * 16) * 128 + wn * 64 + ni * 16,
                acc[mi][ni], 128, wmma::mem_row_major);
    __syncthreads();

    // +bias, coalesced float4 store
    for (int i = tid; i < 128 * 32; i += 256) {
        const int r = i >> 5, c4 = (i & 31) * 4;
        float4 v = *(const float4*)(Dsm + r * 128 + c4);
        v.x += bias[c4];     v.y += bias[c4 + 1];
        v.z += bias[c4 + 2]; v.w += bias[c4 + 3];
        *(float4*)(pre + (size_t)(m0 + r) * G4 + n0 + c4) = v;
    }
}

// ============================================================================
// lstm_rec: gates = pre[t] + h(t-1) @ Whh^T ; persistent, cluster of 4.
// 16 warps: slice sl = (w>>1 + 2*rank)&7 (16 k each), 2 gate rows/thread.
// Own-slice warps (local h cols) run BEFORE cluster wait to hide the barrier.
// ============================================================================
__global__ void __launch_bounds__(512, 1) __cluster_dims__(4, 1, 1)
lstm_rec(const float* __restrict__ pre,   // [T,B,512], biases included
         float* __restrict__ out,         // [T,B,128]
         const float* __restrict__ Whh)   // [512,128]
{
    __shared__ float gbuf[8][8][128];
    __shared__ __align__(16) float hs[2][8][128];

    const int tid = threadIdx.x, lane = tid & 31, w = tid >> 5;
    const int rg = w & 1, slq = w >> 1;
    uint32_t rank;
    asm("mov.u32 %0, %%cluster_ctarank;" : "=r"(rank));
    const int sl = (slq + 2 * (int)rank) & 7;
    const int k0 = sl * 16;
    const bool own = (slq < 2);
    const int b0 = (blockIdx.x >> 2) * 8;

    const int r0 = rg * 64 + lane, r1 = r0 + 32;
    const int gr0 = (r0 >> 5) * H_D + (int)rank * 32 + (r0 & 31);
    const int gr1 = (r1 >> 5) * H_D + (int)rank * 32 + (r1 & 31);

    unsigned long long W0[8], W1[8];
#pragma unroll
    for (int i = 0; i < 8; i++) {
        W0[i] = pack2(Whh[gr0 * H_D + k0 + 2 * i], Whh[gr0 * H_D + k0 + 2 * i + 1]);
        W1[i] = pack2(Whh[gr1 * H_D + k0 + 2 * i], Whh[gr1 * H_D + k0 + 2 * i + 1]);
    }

    const int ob = tid >> 5, oj = tid & 31;
    const int jglob = (int)rank * 32 + oj;
    float c_state = 0.0f;
    const float* pre_p = pre + ((size_t)b0 + ob) * G4 + jglob;
    float* out_p = out + ((size_t)b0 + ob) * H_D + jglob;

    for (int i = tid; i < 8 * H_D; i += 512) hs[0][i >> 7][i & 127] = 0.0f;
    __syncthreads();
    asm volatile("barrier.cluster.arrive.aligned;" ::: "memory");

    for (int t = 0; t < T_SEQ; t++) {
        const int cur = t & 1, nxt = cur ^ 1;

        float p0, p1, p2, p3;
        if (tid < 256) {
            p0 = pre_p[0];   p1 = pre_p[128];
            p2 = pre_p[256]; p3 = pre_p[384];
            pre_p += (size_t)B_SZ * G4;
        }

        if (own) {   // local h columns: ordered by __syncthreads, not barrier
            const float* h0 = &hs[cur][0][k0];
            float* g0 = &gbuf[slq][0][0];
#pragma unroll
            for (int p = 0; p < 2; p++) {
                unsigned long long a0[4] = {0,0,0,0}, a1[4] = {0,0,0,0};
#pragma unroll
                for (int kk = 0; kk < 4; kk++)
#pragma unroll
                    for (int b = 0; b < 4; b++) {
                        ulonglong2 v = *(const ulonglong2*)(h0 + (p * 4 + b) * 128 + 4 * kk);
                        fma2(a0[b], v.x, W0[2 * kk]); fma2(a0[b], v.y, W0[2 * kk + 1]);
                        fma2(a1[b], v.x, W1[2 * kk]); fma2(a1[b], v.y, W1[2 * kk + 1]);
                    }
#pragma unroll
                for (int b = 0; b < 4; b++) {
                    g0[(p * 4 + b) * 128 + r0] = sum2(a0[b]);
                    g0[(p * 4 + b) * 128 + r1] = sum2(a1[b]);
                }
            }
        }

        asm volatile("barrier.cluster.wait.aligned;" ::: "memory");

        if (!own) {  // peer h columns: need the cluster barrier
            const float* h0 = &hs[cur][0][k0];
            float* g0 = &gbuf[slq][0][0];
#pragma unroll
            for (int p = 0; p < 2; p++) {
                unsigned long long a0[4] = {0,0,0,0}, a1[4] = {0,0,0,0};
#pragma unroll
                for (int kk = 0; kk < 4; kk++)
#pragma unroll
                    for (int b = 0; b < 4; b++) {
                        ulonglong2 v = *(const ulonglong2*)(h0 + (p * 4 + b) * 128 + 4 * kk);
                        fma2(a0[b], v.x, W0[2 * kk]); fma2(a0[b], v.y, W0[2 * kk + 1]);
                        fma2(a1[b], v.x, W1[2 * kk]); fma2(a1[b], v.y, W1[2 * kk + 1]);
                    }
#pragma unroll
                for (int b = 0; b < 4; b++) {
                    g0[(p * 4 + b) * 128 + r0] = sum2(a0[b]);
                    g0[(p * 4 + b) * 128 + r1] = sum2(a1[b]);
                }
            }
        }

        __syncthreads();

        if (tid < 256) {
            float gv0 = p0, gv1 = p1, gv2 = p2, gv3 = p3;
#pragma unroll
            for (int q = 0; q < 8; q++) {
                gv0 += gbuf[q][ob][oj];
                gv1 += gbuf[q][ob][32 + oj];
                gv2 += gbuf[q][ob][64 + oj];
                gv3 += gbuf[q][ob][96 + oj];
            }
            const float ig = fsig(gv0), fg = fsig(gv1);
            const float gg = ftanh(gv2), og = fsig(gv3);
            c_state = fg * c_state + ig * gg;
            const float h = og * ftanh(c_state);

            if (t + 1 < T_SEQ) {
                float* hp = &hs[nxt][ob][jglob];
                *hp = h;
                const uint32_t la = (uint32_t)__cvta_generic_to_shared(hp);
#pragma unroll
                for (int pr = 0; pr < 4; pr++)
                    if (pr != (int)rank)
                        asm volatile("{ .reg .b32 ra;\n\t"
                            "mapa.shared::cluster.u32 ra, %0, %1;\n\t"
                            "st.shared::cluster.f32 [ra], %2; }"
                            :: "r"(la), "r"(pr), "f"(h) : "memory");
            }
            *out_p = h;
            out_p += (size_t)B_SZ * H_D;
        }

        if (t + 1 < T_SEQ)
            asm volatile("barrier.cluster.arrive.aligned;" ::: "memory");
        __syncthreads();
    }
}

// ============================================================================
extern "C" void kernel_launch(void* const* d_in, const int* in_sizes, int n_in,
                              void* d_out, int out_size) {
    const float* x     = (const float*)d_in[0];
    const float* Wih0  = (const float*)d_in[1];
    const float* Wrest = (const float*)d_in[2];
    const float* Whh   = (const float*)d_in[3];
    const float* bih   = (const float*)d_in[4];
    const float* bhh   = (const float*)d_in[5];
    float* out = (float*)d_out;

    float *bufA, *bufB, *preb;
    cudaGetSymbolAddress((void**)&bufA, g_bufA);
    cudaGetSymbolAddress((void**)&bufB, g_bufB);
    cudaGetSymbolAddress((void**)&preb, g_pre);

    const int SP64  = 512 + 4 * 128 * 64 * 2;    //  66048 (covers D 64KB reuse)
    const int SP128 = 512 + 4 * 128 * 128 * 2;   // 131584
    cudaFuncSetAttribute(pregemm<64>,
        cudaFuncAttributeMaxDynamicSharedMemorySize, SP64);
    cudaFuncSetAttribute(pregemm<128>,
        cudaFuncAttributeMaxDynamicSharedMemorySize, SP128);

    float* lay_out[5] = {bufA, bufB, bufA, bufB, out};

    pregemm<64><<<4096, 256, SP64>>>(x, Wih0, bih, bhh, preb);
    lstm_rec<<<128, 512>>>(preb, lay_out[0], Whh);
    for (int l = 1; l < 5; l++) {
        pregemm<128><<<4096, 256, SP128>>>(
            lay_out[l - 1], Wrest + (size_t)(l - 1) * G4 * H_D,
            bih + (size_t)l * G4, bhh + (size_t)l * G4, preb);
        lstm_rec<<<128, 512>>>(preb, lay_out[l], Whh + (size_t)l * G4 * H_D);
    }
}